// round 17
// baseline (speedup 1.0000x reference)
#include <cuda_runtime.h>
#include <cuda_bf16.h>

#define ULL unsigned long long

__device__ __forceinline__ ULL add2(ULL a, ULL b) {
    ULL r; asm("add.rn.f32x2 %0, %1, %2;" : "=l"(r) : "l"(a), "l"(b)); return r;
}
__device__ __forceinline__ void unpk2(ULL v, float& lo, float& hi) {
    asm("mov.b64 {%0, %1}, %2;" : "=f"(lo), "=f"(hi) : "l"(v));
}
__device__ __forceinline__ void barw(int id) {   // worker-scoped named barrier, 128 threads
    asm volatile("bar.sync %0, 128;" :: "r"(id) : "memory");
}

// v15: codebook-resident + 5 workers x 128 thr + REGISTER HEADROOM.
// grid = #SMs, 1 block/SM, 640 threads = 5 workers (4 warps each).
// Reg cap at 640 thr = 102/thread (R11-R13 all sat at their 72-85 caps ->
// ptxas couldn't batch the 8 LDS/dq deep, short-scoreboard stalls capped
// issue at ~59% for six rounds).
// Codebook (128 KB) staged once. Quantum = 4 states x 512 cells; 2048 quanta
// over 760 chains -> 13-14 quanta/SM (7.7% tail).
// x prefetched into REGISTERS (plain LDG) one quantum ahead; negated at STS
// so the inner loop is 2-source add2 (rt 2; the 3-source fma2 risks RF-bank rt 3).
// Thread tile S=4 states x C=4 cells; acc = 16 ULL = 32 regs.
__global__ __launch_bounds__(640, 1) void PlaceCells_kernel(
    const float* __restrict__ x, const float* __restrict__ pc,
    float* __restrict__ out, int nblocks)
{
    extern __shared__ char smem[];
    float4* cs4 = reinterpret_cast<float4*>(smem);            // [16 dq][512 cells] = 128 KB
    float4* xsw = reinterpret_cast<float4*>(smem + 131072);   // [5 wk][2 buf][64] = 10 KB
    float*  wmp = reinterpret_cast<float*>(smem + 131072 + 10240);        // [5][4 warp][4 st]
    float*  wsp = reinterpret_cast<float*>(smem + 131072 + 10240 + 320);  // [5][4 warp][4 st]

    const int tid  = threadIdx.x;
    const int wk   = tid >> 7;        // worker 0..4
    const int wt   = tid & 127;       // thread-in-worker (cell thread)
    const int lane = tid & 31;
    const int ww   = wt >> 5;         // warp-in-worker 0..3

    // ---- stage full codebook once: cs4[dq*512 + cell] ----
    if (tid < 512) {
        const float4* pc4 = reinterpret_cast<const float4*>(pc);
        #pragma unroll
        for (int i = 0; i < 16; i++)
            cs4[i * 512 + tid] = pc4[tid * 16 + i];
    }

    const float4* x4 = reinterpret_cast<const float4*>(x);
    const ulonglong2* csU = reinterpret_cast<const ulonglong2*>(cs4);
    const ulonglong2* xwU = reinterpret_cast<const ulonglong2*>(xsw + wk * 128);
    float4* myxs = xsw + wk * 128;
    const ULL ABSM = 0x7FFFFFFF7FFFFFFFULL;

    const int chain = wk * nblocks + blockIdx.x;   // 0..5*nblocks-1
    const int NCH   = 5 * nblocks;
    const bool prod = (wt < 64);                   // x-staging producer threads

    __syncthreads();    // codebook visible (only block-wide barrier)

    // ---- prologue: prefetch x for first quantum into registers ----
    float4 xreg = make_float4(0.f, 0.f, 0.f, 0.f);
    if (chain < 2048 && prod)
        xreg = x4[(ULL)chain * 64 + wt];           // 4 states x 16 dq, contiguous

    for (int m = 0; ; m++) {
        const int q = chain + NCH * m;
        if (q >= 2048) break;
        const int buf = m & 1;
        const int bs  = q * 4;                     // first state of quantum

        // ---- stage -x (from prefetched regs) into buf ----
        if (prod)
            myxs[buf * 64 + wt] = make_float4(-xreg.x, -xreg.y, -xreg.z, -xreg.w);
        barw(wk + 1);                              // x tile visible to worker

        // prefetch next quantum's x into registers (latency hidden by mainloop)
        const int qn = q + NCH;
        if (qn < 2048 && prod)
            xreg = x4[(ULL)qn * 64 + wt];

        // ---- mainloop: S=4 states x C=4 cells, fully unrolled ----
        ULL acc[4][4];
        #pragma unroll
        for (int i = 0; i < 4; i++)
            #pragma unroll
            for (int j = 0; j < 4; j++) acc[i][j] = 0ULL;

        #pragma unroll
        for (int dq = 0; dq < 16; dq++) {
            ulonglong2 nx[4];
            #pragma unroll
            for (int i = 0; i < 4; i++)
                nx[i] = xwU[buf * 64 + i * 16 + dq];        // warp-uniform broadcast
            #pragma unroll
            for (int j = 0; j < 4; j++) {
                ulonglong2 cv = csU[dq * 512 + wt + j * 128];   // conflict-free
                #pragma unroll
                for (int i = 0; i < 4; i++) {
                    ULL d0 = add2(cv.x, nx[i].x) & ABSM;   // |c - x| on 2 dims
                    ULL d1 = add2(cv.y, nx[i].y) & ABSM;
                    acc[i][j] = add2(acc[i][j], d0);
                    acc[i][j] = add2(acc[i][j], d1);
                }
            }
        }

        // ---- logits u = -0.5 * l1^2 ----
        float u[4][4];
        #pragma unroll
        for (int i = 0; i < 4; i++)
            #pragma unroll
            for (int j = 0; j < 4; j++) {
                float lo, hi; unpk2(acc[i][j], lo, hi);
                float l1 = lo + hi;
                u[i][j] = -0.5f * l1 * l1;
            }

        // ---- per-warp partial (pm, ps) per state; cache exps in u ----
        float pmv[4];
        #pragma unroll
        for (int i = 0; i < 4; i++) {
            float pm = fmaxf(fmaxf(u[i][0], u[i][1]), fmaxf(u[i][2], u[i][3]));
            #pragma unroll
            for (int off = 16; off > 0; off >>= 1)
                pm = fmaxf(pm, __shfl_xor_sync(0xffffffffu, pm, off));
            float ps = 0.0f;
            #pragma unroll
            for (int j = 0; j < 4; j++) {
                float e = __expf(u[i][j] - pm);
                u[i][j] = e;                      // cache exp for output
                ps += e;
            }
            #pragma unroll
            for (int off = 16; off > 0; off >>= 1)
                ps += __shfl_xor_sync(0xffffffffu, ps, off);
            pmv[i] = pm;
            if (lane == 0) {
                wmp[(wk * 4 + ww) * 4 + i] = pm;
                wsp[(wk * 4 + ww) * 4 + i] = ps;
            }
        }
        barw(wk + 1);   // partials visible within worker

        // ---- lane-parallel merge of 4 warp-partials per state ----
        const int k = lane & 3;
        #pragma unroll
        for (int i = 0; i < 4; i++) {
            float mk = wmp[(wk * 4 + k) * 4 + i];
            float M  = mk;
            M = fmaxf(M, __shfl_xor_sync(0xffffffffu, M, 2));
            M = fmaxf(M, __shfl_xor_sync(0xffffffffu, M, 1));
            float sk = wsp[(wk * 4 + k) * 4 + i] * __expf(mk - M);
            sk += __shfl_xor_sync(0xffffffffu, sk, 2);
            sk += __shfl_xor_sync(0xffffffffu, sk, 1);
            float scale = __expf(pmv[i] - M) / sk;
            const ULL srow = (ULL)(bs + i);
            #pragma unroll
            for (int j = 0; j < 4; j++)
                out[srow * 512 + wt + j * 128] = u[i][j] * scale;
        }
    }
}

extern "C" void kernel_launch(void* const* d_in, const int* in_sizes, int n_in,
                              void* d_out, int out_size) {
    const float* a = (const float*)d_in[0];
    const float* b = (const float*)d_in[1];
    // x is the larger tensor (8192*64), placeCells is 512*64
    const float* x  = (in_sizes[0] >= in_sizes[1]) ? a : b;
    const float* pc = (in_sizes[0] >= in_sizes[1]) ? b : a;

    const int dyn_smem = 131072 + 10240 + 640;  // codebook + x buffers + partials

    static int nsm = 0;
    if (!nsm) {
        cudaDeviceGetAttribute(&nsm, cudaDevAttrMultiProcessorCount, 0);
        if (nsm <= 0) nsm = 148;
        cudaFuncSetAttribute(PlaceCells_kernel,
                             cudaFuncAttributeMaxDynamicSharedMemorySize, dyn_smem);
    }
    PlaceCells_kernel<<<nsm, 640, dyn_smem>>>(x, pc, (float*)d_out, nsm);
}